// round 10
// baseline (speedup 1.0000x reference)
#include <cuda_runtime.h>
#include <cuda_bf16.h>
#include <math.h>

// Problem shape (fixed by the dataset):
//   B=64, T=512, D_in=256, D_out=1024, M=8 (module_size=128)
// Inputs: x[B,T,Din], W_in[Din,Dout], b_in[Dout], W_h[Dout,Dout],
//         periods[M], shifts[M]
// Output: ys[B,T,Dout] (33554432 floats) then h_final[B,Dout].
//
// Phase 1: u = x@W_in + b_in into the ys region of d_out (f32x2 GEMM).
// Phase 2: persistent 128-CTA x 512-thread recurrence, 2-D decomposition:
//   4 row-groups x 32 col-groups -> each CTA does 16 rows x 32 cols, reading
//   only 64 KB of h per step (8 MB/step chip-wide). 16-way split-K, 8-deep
//   LDG.cg prefetch ring, fma.rn.f32x2 mainloop, full-512-thread tail.
//   Barrier: R5's PROVEN flag-tree (per-CTA padded flags, CTA0 polls,
//   single-word broadcast release) — single-address spin so polling CTAs
//   don't flood L2 while laggards finish their k-loop.

#define B_      64
#define T_      512
#define DIN     256
#define DOUT    1024
#define BSTR    ((size_t)T_ * DOUT)
#define YS_ELEMS ((size_t)B_ * T_ * DOUT)

typedef unsigned long long ull;

// ---------------------------------------------------------------------------
// Packed-fp32 helpers (Blackwell f32x2)
// ---------------------------------------------------------------------------
__device__ __forceinline__ ull dupf(float x) {
    ull r;
    asm("mov.b64 %0, {%1, %1};" : "=l"(r) : "f"(x));
    return r;
}
__device__ __forceinline__ void ffma2(ull& d, ull a, ull b) {
    asm("fma.rn.f32x2 %0, %1, %2, %0;" : "+l"(d) : "l"(a), "l"(b));
}
__device__ __forceinline__ ull addf2(ull a, ull b) {
    ull r;
    asm("add.rn.f32x2 %0, %1, %2;" : "=l"(r) : "l"(a), "l"(b));
    return r;
}
__device__ __forceinline__ ull duplo(ull v) {
    ull r;
    asm("{\n\t.reg .b32 a,b;\n\tmov.b64 {a,b}, %1;\n\tmov.b64 %0, {a,a};\n\t}"
        : "=l"(r) : "l"(v));
    return r;
}
__device__ __forceinline__ ull duphi(ull v) {
    ull r;
    asm("{\n\t.reg .b32 a,b;\n\tmov.b64 {a,b}, %1;\n\tmov.b64 %0, {b,b};\n\t}"
        : "=l"(r) : "l"(v));
    return r;
}
__device__ __forceinline__ ull ldcg_u64(const float* p) {
    ull r;
    asm volatile("ld.global.cg.b64 %0, [%1];" : "=l"(r) : "l"(p));
    return r;
}

// ---------------------------------------------------------------------------
// Phase 1: u = X @ W_in + b_in     (M=32768, N=1024, K=256)
// ---------------------------------------------------------------------------
__global__ void __launch_bounds__(256) phase1_gemm(
    const float* __restrict__ X, const float* __restrict__ Win,
    const float* __restrict__ bin, float* __restrict__ out)
{
    __shared__ float As[16 * 132];
    __shared__ float Bs[16 * 68];

    const int tid = threadIdx.x;
    const int tn0 = blockIdx.x * 64;
    const int tm0 = blockIdx.y * 128;
    const int ty  = tid >> 4;
    const int tx  = tid & 15;

    ull acc01[8], acc23[8];
#pragma unroll
    for (int i = 0; i < 8; i++) { acc01[i] = 0ull; acc23[i] = 0ull; }

    const int arow  = tid >> 1;
    const int akoff = (tid & 1) * 8;
    const int bk    = tid >> 4;
    const int bn    = (tid & 15) * 4;

    for (int kc = 0; kc < DIN; kc += 16) {
        const float* ap = &X[(size_t)(tm0 + arow) * DIN + kc + akoff];
        float4 a0 = *(const float4*)(ap);
        float4 a1 = *(const float4*)(ap + 4);
        float4 b0 = *(const float4*)&Win[(size_t)(kc + bk) * DOUT + tn0 + bn];

        __syncthreads();
        As[(akoff + 0) * 132 + arow] = a0.x;
        As[(akoff + 1) * 132 + arow] = a0.y;
        As[(akoff + 2) * 132 + arow] = a0.z;
        As[(akoff + 3) * 132 + arow] = a0.w;
        As[(akoff + 4) * 132 + arow] = a1.x;
        As[(akoff + 5) * 132 + arow] = a1.y;
        As[(akoff + 6) * 132 + arow] = a1.z;
        As[(akoff + 7) * 132 + arow] = a1.w;
        *(float4*)&Bs[bk * 68 + bn] = b0;
        __syncthreads();

#pragma unroll
        for (int kk = 0; kk < 16; kk++) {
            float4 af0 = *(const float4*)&As[kk * 132 + ty * 8];
            float4 af1 = *(const float4*)&As[kk * 132 + ty * 8 + 4];
            ulonglong2 bb = *(const ulonglong2*)&Bs[kk * 68 + tx * 4];
            float a[8] = {af0.x, af0.y, af0.z, af0.w, af1.x, af1.y, af1.z, af1.w};
#pragma unroll
            for (int i = 0; i < 8; i++) {
                ull ad = dupf(a[i]);
                ffma2(acc01[i], ad, bb.x);
                ffma2(acc23[i], ad, bb.y);
            }
        }
    }

    ulonglong2 bp = *(const ulonglong2*)&bin[tn0 + tx * 4];
#pragma unroll
    for (int i = 0; i < 8; i++) {
        ulonglong2 st;
        st.x = addf2(acc01[i], bp.x);
        st.y = addf2(acc23[i], bp.y);
        *(ulonglong2*)&out[(size_t)(tm0 + ty * 8 + i) * DOUT + tn0 + tx * 4] = st;
    }
}

// ---------------------------------------------------------------------------
// Phase 2: persistent recurrence. 128 CTAs x 512 threads.
// CTA (rowg = bid>>5, colg = bid&31) owns rows [16*rowg,+16) x cols [32*colg,+32).
// ---------------------------------------------------------------------------
#define NB2 128
#define NW2 16          // warps per CTA (k-slices)
#define KSL 64          // k per warp
#define SWBYTES (DOUT * 16 * 8)                  // 128 KB W (float2[k][16 pairs])
#define SMEM2   (SWBYTES + NW2 * 8 * 32 * 8)     // + 32 KB partials

// Transposed hidden state, double-buffered by t parity: g_hT[buf][j*64 + r].
__device__ float g_hT[2][DOUT * B_];

// Flag-tree grid barrier state (R5-proven). Per-CTA flags padded 128B apart.
__device__ volatile unsigned g_flag[NB2 * 32];
__device__ volatile unsigned g_gen2;

// Grid barrier: CTA stores its step to a private flag (no contention);
// CTA 0 warp 0 polls all flags and broadcasts via g_gen2 (single word ->
// L2-friendly same-address spin for the other 127 CTAs). Equality compares
// + strictly increasing targets make this replay-safe (the only stale value,
// 512 from the previous replay, is first compared against 1).
__device__ __forceinline__ void gsync(int bid, unsigned target)
{
    __syncthreads();
    if (threadIdx.x < 32) {
        if (threadIdx.x == 0) {
            __threadfence();
            g_flag[bid << 5] = target;
        }
        if (bid == 0) {
            bool done;
            do {
                done = true;
#pragma unroll
                for (int c = threadIdx.x; c < NB2; c += 32)
                    if (g_flag[c << 5] != target) done = false;
            } while (!__all_sync(0xffffffffu, done));
            if (threadIdx.x == 0) {
                __threadfence();
                g_gen2 = target;
            }
        } else if (threadIdx.x == 0) {
            while (g_gen2 != target) { }
            __threadfence();
        }
    }
    __syncthreads();
}

__global__ void __launch_bounds__(512) phase2_rnn(
    const float* __restrict__ Wh, const float* __restrict__ periods,
    const float* __restrict__ shifts, float* __restrict__ out)
{
    extern __shared__ char smem_raw[];
    float2* sW = (float2*)smem_raw;              // [k][16 col-pairs], 128 KB
    ull*    sP = (ull*)(smem_raw + SWBYTES);     // [w][slot][lane^..], 32 KB

    const int tid  = threadIdx.x;
    const int bid  = blockIdx.x;
    const int colg = bid & 31;
    const int j0   = colg * 32;                  // first of 32 cols
    const int r0   = (bid >> 5) * 16;            // first of 16 rows
    const int w    = tid >> 5;                   // warp = k-slice (0..15)
    const int l    = tid & 31;
    const int rp   = l & 7;                      // row-pair within 16 rows
    const int ch   = l >> 3;                     // 8-col chunk (0..3)

    // One-time: this CTA's 32 W_h columns as col-pairs (128 KB).
    for (int i = tid; i < DOUT * 16; i += 512) {
        int k = i >> 4, cp = i & 15;
        sW[i] = make_float2(Wh[(size_t)k * DOUT + j0 + 2 * cp],
                            Wh[(size_t)k * DOUT + j0 + 2 * cp + 1]);
    }
    // 32-col group lies inside one module (module size 128).
    const float per = periods[colg >> 2];
    const float shf = shifts[colg >> 2];

    // Output mapping: one scalar per thread. c = col-in-CTA, rl = row-in-CTA.
    const int c    = tid & 31;
    const int rl   = tid >> 5;                   // 0..15
    const int gr   = r0 + rl;                    // global row (batch index)
    const int ej   = j0 + c;                     // global col
    // Reduction coordinates: producing lane, slot, half.
    const int s    = ((rl & 1) << 2) + ((c & 7) >> 1);
    const int lx   = ((((c >> 3) << 3) + (rl >> 1)) ^ (s << 1));
    const int half = c & 1;
    __syncthreads();

    // ---- t = 0: h_prev = 0 -> y = (1-g) * tanh(u). ----
    {
        float g = (sinf(shf) + 1.f) * 0.5f;
        size_t ob = (size_t)gr * BSTR + ej;
        float y = (1.f - g) * tanhf(out[ob]);
        out[ob] = y;
        g_hT[0][ej * B_ + gr] = y;
    }
    gsync(bid, 1u);

    const int kbase = w << 6;                    // warp's K-slice base

    for (int t = 1; t < T_; t++) {
        const float* __restrict__ hsrc = g_hT[(t - 1) & 1];
        float*       __restrict__ hdst = g_hT[t & 1];

        // Mainloop: 64 k per warp, 8-deep LDG.cg prefetch ring.
        // Each lane: rows (r0+2rp, r0+2rp+1) x cols [j0+8ch, +8).
        const float* hs = hsrc + (kbase << 6) + r0 + (rp << 1);
        ull a0 = 0, a1 = 0, a2 = 0, a3 = 0, a4 = 0, a5 = 0, a6 = 0, a7 = 0;
        ull hbuf[8];
#pragma unroll
        for (int j = 0; j < 8; j++) hbuf[j] = ldcg_u64(hs + (j << 6));

        // Hoisted epilogue loads hide under the mainloop.
        size_t ob = (size_t)gr * BSTR + (size_t)t * DOUT + ej;
        float uv = __ldcg(&out[ob]);
        float hp = __ldcg(&hsrc[ej * B_ + gr]);

#pragma unroll
        for (int kk = 0; kk < KSL; kk += 8) {
#pragma unroll
            for (int j = 0; j < 8; j++) {
                ull hp64 = hbuf[j];
                const int knext = kk + 8 + j;
                if (knext < KSL) hbuf[j] = ldcg_u64(hs + (knext << 6));
                const ulonglong2* wp =
                    (const ulonglong2*)&sW[((kbase + kk + j) << 4) + (ch << 2)];
                ulonglong2 wA = wp[0];           // cols 8ch+0..3
                ulonglong2 wB = wp[1];           // cols 8ch+4..7
                ull hd0 = duplo(hp64);
                ull hd1 = duphi(hp64);
                ffma2(a0, hd0, wA.x); ffma2(a1, hd0, wA.y);
                ffma2(a2, hd0, wB.x); ffma2(a3, hd0, wB.y);
                ffma2(a4, hd1, wA.x); ffma2(a5, hd1, wA.y);
                ffma2(a6, hd1, wB.x); ffma2(a7, hd1, wB.y);
            }
        }

        // Partials: slot s2 = rowparity*4 + colpair, lane XOR-swizzled.
#define STP(s2, v) sP[((w << 3) + (s2)) * 32 + (l ^ ((s2) << 1))] = (v)
        STP(0, a0); STP(1, a1); STP(2, a2); STP(3, a3);
        STP(4, a4); STP(5, a5); STP(6, a6); STP(7, a7);
#undef STP
        __syncthreads();

        // Full-width tail: every thread reduces 16 partials (tree) for its
        // (rl, c) output, then applies tanh + gate.
        const float* sPf = (const float*)sP;
        float p[16];
#pragma unroll
        for (int w2 = 0; w2 < NW2; w2++)
            p[w2] = sPf[(((((w2 << 3) + s) << 5) + lx) << 1) + half];
        float s01 = p[0] + p[1],   s23 = p[2] + p[3];
        float s45 = p[4] + p[5],   s67 = p[6] + p[7];
        float s89 = p[8] + p[9],   sab = p[10] + p[11];
        float scd = p[12] + p[13], sef = p[14] + p[15];
        float q0 = s01 + s23, q1 = s45 + s67, q2 = s89 + sab, q3 = scd + sef;
        float hv = (q0 + q1) + (q2 + q3);

        float g = (sinf((float)t * per + shf) + 1.f) * 0.5f;
        float y = (1.f - g) * tanhf(uv + hv) + g * hp;
        out[ob] = y;
        hdst[ej * B_ + gr] = y;

        gsync(bid, (unsigned)(t + 1));           // also fences sP reuse
    }

    // h_final = ys[:, T-1, :]  (cross-CTA reads -> .cg)
    for (int idx = bid * 512 + tid; idx < B_ * DOUT; idx += NB2 * 512) {
        int b = idx >> 10, j = idx & (DOUT - 1);
        out[YS_ELEMS + idx] =
            __ldcg(&out[(size_t)b * BSTR + (size_t)(T_ - 1) * DOUT + j]);
    }
}

// ---------------------------------------------------------------------------
extern "C" void kernel_launch(void* const* d_in, const int* in_sizes, int n_in,
                              void* d_out, int out_size)
{
    (void)in_sizes; (void)n_in; (void)out_size;
    const float* x       = (const float*)d_in[0];
    const float* W_in    = (const float*)d_in[1];
    const float* b_in    = (const float*)d_in[2];
    const float* W_h     = (const float*)d_in[3];
    const float* periods = (const float*)d_in[4];
    const float* shifts  = (const float*)d_in[5];
    float* out = (float*)d_out;

    // Opt-in smem above 48 KB (function-state call, capture-legal).
    cudaFuncSetAttribute(phase2_rnn,
                         cudaFuncAttributeMaxDynamicSharedMemorySize, SMEM2);

    dim3 g1(DOUT / 64, (B_ * T_) / 128);       // (16, 256)
    phase1_gemm<<<g1, 256>>>(x, W_in, b_in, out);
    phase2_rnn<<<NB2, 512, SMEM2>>>(W_h, periods, shifts, out);
}

// round 11
// speedup vs baseline: 1.7181x; 1.7181x over previous
#include <cuda_runtime.h>
#include <cuda_bf16.h>
#include <math.h>

// Problem shape (fixed by the dataset):
//   B=64, T=512, D_in=256, D_out=1024, M=8 (module_size=128)
// Inputs: x[B,T,Din], W_in[Din,Dout], b_in[Dout], W_h[Dout,Dout],
//         periods[M], shifts[M]
// Output: ys[B,T,Dout] (33554432 floats) then h_final[B,Dout].
//
// Phase 1: u = x@W_in + b_in into the ys region of d_out (f32x2 GEMM).
// Phase 2: persistent 128-CTA x 512-thread recurrence (PROVEN 1-D layout:
//   each CTA owns 8 cols x all 64 rows; 16-way split-K; 256B/warp coalesced
//   h loads). This round: prefetch ring deepened 8 -> 16 to cover L2 latency
//   (~234-260 cyc) and __launch_bounds__(512,1) to unlock the register
//   budget for it. Flag-tree grid barrier (R5-proven).

#define B_      64
#define T_      512
#define DIN     256
#define DOUT    1024
#define BSTR    ((size_t)T_ * DOUT)
#define YS_ELEMS ((size_t)B_ * T_ * DOUT)

typedef unsigned long long ull;

// ---------------------------------------------------------------------------
// Packed-fp32 helpers (Blackwell f32x2)
// ---------------------------------------------------------------------------
__device__ __forceinline__ ull dupf(float x) {
    ull r;
    asm("mov.b64 %0, {%1, %1};" : "=l"(r) : "f"(x));
    return r;
}
__device__ __forceinline__ void ffma2(ull& d, ull a, ull b) {
    asm("fma.rn.f32x2 %0, %1, %2, %0;" : "+l"(d) : "l"(a), "l"(b));
}
__device__ __forceinline__ ull addf2(ull a, ull b) {
    ull r;
    asm("add.rn.f32x2 %0, %1, %2;" : "=l"(r) : "l"(a), "l"(b));
    return r;
}
__device__ __forceinline__ float2 unpk(ull v) {
    float2 r;
    asm("mov.b64 {%0, %1}, %2;" : "=f"(r.x), "=f"(r.y) : "l"(v));
    return r;
}
__device__ __forceinline__ ull duplo(ull v) {
    ull r;
    asm("{\n\t.reg .b32 a,b;\n\tmov.b64 {a,b}, %1;\n\tmov.b64 %0, {a,a};\n\t}"
        : "=l"(r) : "l"(v));
    return r;
}
__device__ __forceinline__ ull duphi(ull v) {
    ull r;
    asm("{\n\t.reg .b32 a,b;\n\tmov.b64 {a,b}, %1;\n\tmov.b64 %0, {b,b};\n\t}"
        : "=l"(r) : "l"(v));
    return r;
}
__device__ __forceinline__ ull ldcg_u64(const float* p) {
    ull r;
    asm volatile("ld.global.cg.b64 %0, [%1];" : "=l"(r) : "l"(p));
    return r;
}

// ---------------------------------------------------------------------------
// Phase 1: u = X @ W_in + b_in     (M=32768, N=1024, K=256)
// ---------------------------------------------------------------------------
__global__ void __launch_bounds__(256) phase1_gemm(
    const float* __restrict__ X, const float* __restrict__ Win,
    const float* __restrict__ bin, float* __restrict__ out)
{
    __shared__ float As[16 * 132];
    __shared__ float Bs[16 * 68];

    const int tid = threadIdx.x;
    const int tn0 = blockIdx.x * 64;
    const int tm0 = blockIdx.y * 128;
    const int ty  = tid >> 4;
    const int tx  = tid & 15;

    ull acc01[8], acc23[8];
#pragma unroll
    for (int i = 0; i < 8; i++) { acc01[i] = 0ull; acc23[i] = 0ull; }

    const int arow  = tid >> 1;
    const int akoff = (tid & 1) * 8;
    const int bk    = tid >> 4;
    const int bn    = (tid & 15) * 4;

    for (int kc = 0; kc < DIN; kc += 16) {
        const float* ap = &X[(size_t)(tm0 + arow) * DIN + kc + akoff];
        float4 a0 = *(const float4*)(ap);
        float4 a1 = *(const float4*)(ap + 4);
        float4 b0 = *(const float4*)&Win[(size_t)(kc + bk) * DOUT + tn0 + bn];

        __syncthreads();
        As[(akoff + 0) * 132 + arow] = a0.x;
        As[(akoff + 1) * 132 + arow] = a0.y;
        As[(akoff + 2) * 132 + arow] = a0.z;
        As[(akoff + 3) * 132 + arow] = a0.w;
        As[(akoff + 4) * 132 + arow] = a1.x;
        As[(akoff + 5) * 132 + arow] = a1.y;
        As[(akoff + 6) * 132 + arow] = a1.z;
        As[(akoff + 7) * 132 + arow] = a1.w;
        *(float4*)&Bs[bk * 68 + bn] = b0;
        __syncthreads();

#pragma unroll
        for (int kk = 0; kk < 16; kk++) {
            float4 af0 = *(const float4*)&As[kk * 132 + ty * 8];
            float4 af1 = *(const float4*)&As[kk * 132 + ty * 8 + 4];
            ulonglong2 bb = *(const ulonglong2*)&Bs[kk * 68 + tx * 4];
            float a[8] = {af0.x, af0.y, af0.z, af0.w, af1.x, af1.y, af1.z, af1.w};
#pragma unroll
            for (int i = 0; i < 8; i++) {
                ull ad = dupf(a[i]);
                ffma2(acc01[i], ad, bb.x);
                ffma2(acc23[i], ad, bb.y);
            }
        }
    }

    ulonglong2 bp = *(const ulonglong2*)&bin[tn0 + tx * 4];
#pragma unroll
    for (int i = 0; i < 8; i++) {
        ulonglong2 st;
        st.x = addf2(acc01[i], bp.x);
        st.y = addf2(acc23[i], bp.y);
        *(ulonglong2*)&out[(size_t)(tm0 + ty * 8 + i) * DOUT + tn0 + tx * 4] = st;
    }
}

// ---------------------------------------------------------------------------
// Phase 2: persistent recurrence. 128 CTAs x 512 threads, 8 cols per CTA.
// ---------------------------------------------------------------------------
#define NB2 128
#define NW2 16          // warps per CTA (k-slices)
#define KSL 64          // k per warp
#define PFD 16          // prefetch ring depth (covers ~416 cyc > L2 latency)
#define SMEM2 (DOUT * 4 * 8 + NW2 * 8 * 32 * 8)   // 32 KB sW + 32 KB sP

// Transposed hidden state, double-buffered by t parity: g_hT[buf][j*64 + r].
__device__ float g_hT[2][DOUT * B_];

// Flag-tree grid barrier state. Per-CTA flags padded 128B apart.
__device__ volatile unsigned g_flag[NB2 * 32];
__device__ volatile unsigned g_gen2;

// Grid barrier: CTA stores its step to a private flag (no contention);
// CTA 0 warp 0 polls all flags and broadcasts via g_gen2 (single word ->
// L2-friendly same-address spin for the other 127 CTAs). Equality compares
// + strictly increasing targets make this replay-safe (the only stale value,
// 512 from the previous replay, is first compared against 1).
__device__ __forceinline__ void gsync(int bid, unsigned target)
{
    __syncthreads();
    if (threadIdx.x < 32) {
        if (threadIdx.x == 0) {
            __threadfence();
            g_flag[bid << 5] = target;
        }
        if (bid == 0) {
            bool done;
            do {
                done = true;
#pragma unroll
                for (int c = threadIdx.x; c < NB2; c += 32)
                    if (g_flag[c << 5] != target) done = false;
            } while (!__all_sync(0xffffffffu, done));
            if (threadIdx.x == 0) {
                __threadfence();
                g_gen2 = target;
            }
        } else if (threadIdx.x == 0) {
            while (g_gen2 != target) { }
            __threadfence();
        }
    }
    __syncthreads();
}

__global__ void __launch_bounds__(512, 1) phase2_rnn(
    const float* __restrict__ Wh, const float* __restrict__ periods,
    const float* __restrict__ shifts, float* __restrict__ out)
{
    extern __shared__ char smem_raw[];
    float2* sW = (float2*)smem_raw;                      // [k][col-pair], 32 KB
    ull*    sP = (ull*)(smem_raw + DOUT * 4 * 8);        // [w][slot][lane^..], 32 KB

    const int tid = threadIdx.x;
    const int bid = blockIdx.x;
    const int j0  = bid * 8;
    const int w   = tid >> 5;                // warp = k-slice (0..15)
    const int l   = tid & 31;                // lane -> rows (2l, 2l+1)

    // One-time: this CTA's 8 W_h columns as col-pairs.
    for (int i = tid; i < DOUT * 4; i += 512) {
        int k = i >> 2, cp = i & 3;
        sW[i] = make_float2(Wh[(size_t)k * DOUT + j0 + 2 * cp],
                            Wh[(size_t)k * DOUT + j0 + 2 * cp + 1]);
    }
    const float per = periods[bid >> 4];
    const float shf = shifts[bid >> 4];

    // Epilogue mapping (tid < 256): thread -> (row er, col-pair ecp).
    const int er   = (tid & 255) >> 2;       // 0..63
    const int ecp  = tid & 3;                // 0..3
    const int ej   = j0 + 2 * ecp;
    const int sres = ((er & 1) << 2) + ecp;  // slot 0..7
    const int rrow = er >> 1;                // 0..31
    __syncthreads();

    // ---- t = 0: h_prev = 0 -> y = (1-g) * tanh(u). ----
    if (tid < 256) {
        float g = (sinf(shf) + 1.f) * 0.5f;
        size_t ob = (size_t)er * BSTR + ej;
        float2 u = *(const float2*)&out[ob];
        float2 y;
        y.x = (1.f - g) * tanhf(u.x);
        y.y = (1.f - g) * tanhf(u.y);
        *(float2*)&out[ob] = y;
        g_hT[0][ej * B_ + er]       = y.x;
        g_hT[0][(ej + 1) * B_ + er] = y.y;
    }
    gsync(bid, 1u);

    const int kbase = w << 6;                // this warp's K-slice base

    for (int t = 1; t < T_; t++) {
        const float* __restrict__ hsrc = g_hT[(t - 1) & 1];
        float*       __restrict__ hdst = g_hT[t & 1];

        // Hoist epilogue loads so their latency hides under the mainloop.
        float2 uv = make_float2(0.f, 0.f), hpv = make_float2(0.f, 0.f);
        size_t ob = 0;
        if (tid < 256) {
            ob  = (size_t)er * BSTR + (size_t)t * DOUT + ej;
            uv  = *(const float2*)&out[ob];
            hpv.x = __ldcg(&hsrc[ej * B_ + er]);
            hpv.y = __ldcg(&hsrc[(ej + 1) * B_ + er]);
        }

        // Mainloop: 64 k per warp, 16-deep LDG.cg prefetch ring
        // (256B/warp coalesced; depth covers L2 latency).
        const float* hs = hsrc + (kbase << 6) + (l << 1);
        ull a0 = 0, a1 = 0, a2 = 0, a3 = 0, a4 = 0, a5 = 0, a6 = 0, a7 = 0;
        ull hbuf[PFD];
#pragma unroll
        for (int j = 0; j < PFD; j++) hbuf[j] = ldcg_u64(hs + (j << 6));

#pragma unroll
        for (int kk = 0; kk < KSL; kk += PFD) {
#pragma unroll
            for (int j = 0; j < PFD; j++) {
                ull hp = hbuf[j];
                const int knext = kk + PFD + j;
                if (knext < KSL) hbuf[j] = ldcg_u64(hs + (knext << 6));
                const ulonglong2* wp =
                    (const ulonglong2*)&sW[(kbase + kk + j) << 2];
                ulonglong2 wA = wp[0];       // {c0c1, c2c3} (broadcast)
                ulonglong2 wB = wp[1];       // {c4c5, c6c7}
                ull hd0 = duplo(hp);
                ull hd1 = duphi(hp);
                ffma2(a0, hd0, wA.x); ffma2(a1, hd0, wA.y);
                ffma2(a2, hd0, wB.x); ffma2(a3, hd0, wB.y);
                ffma2(a4, hd1, wA.x); ffma2(a5, hd1, wA.y);
                ffma2(a6, hd1, wB.x); ffma2(a7, hd1, wB.y);
            }
        }

        // Partials to smem: slot s = rr*4 + cp, lane XOR-swizzled by (s<<1).
#define STP(s, v) sP[((w << 3) + (s)) * 32 + (l ^ ((s) << 1))] = (v)
        STP(0, a0); STP(1, a1); STP(2, a2); STP(3, a3);
        STP(4, a4); STP(5, a5); STP(6, a6); STP(7, a7);
#undef STP
        __syncthreads();

        // 16-way cross-warp reduction + epilogue (tid < 256).
        if (tid < 256) {
            const int lx = rrow ^ (sres << 1);
            ull sum = sP[(sres << 5) + lx];
#pragma unroll
            for (int w2 = 1; w2 < NW2; w2++)
                sum = addf2(sum, sP[(((w2 << 3) + sres) << 5) + lx]);
            float2 hv = unpk(sum);

            float g = (sinf((float)t * per + shf) + 1.f) * 0.5f;
            float2 y;
            y.x = (1.f - g) * tanhf(uv.x + hv.x) + g * hpv.x;
            y.y = (1.f - g) * tanhf(uv.y + hv.y) + g * hpv.y;
            *(float2*)&out[ob] = y;
            hdst[ej * B_ + er]       = y.x;
            hdst[(ej + 1) * B_ + er] = y.y;
        }

        gsync(bid, (unsigned)(t + 1));       // also fences sP reuse
    }

    // h_final = ys[:, T-1, :]  (cross-CTA reads -> .cg)
    for (int idx = bid * 512 + tid; idx < B_ * DOUT; idx += NB2 * 512) {
        int b = idx >> 10, j = idx & (DOUT - 1);
        out[YS_ELEMS + idx] =
            __ldcg(&out[(size_t)b * BSTR + (size_t)(T_ - 1) * DOUT + j]);
    }
}

// ---------------------------------------------------------------------------
extern "C" void kernel_launch(void* const* d_in, const int* in_sizes, int n_in,
                              void* d_out, int out_size)
{
    (void)in_sizes; (void)n_in; (void)out_size;
    const float* x       = (const float*)d_in[0];
    const float* W_in    = (const float*)d_in[1];
    const float* b_in    = (const float*)d_in[2];
    const float* W_h     = (const float*)d_in[3];
    const float* periods = (const float*)d_in[4];
    const float* shifts  = (const float*)d_in[5];
    float* out = (float*)d_out;

    // Opt-in smem above 48 KB (function-state call, capture-legal).
    cudaFuncSetAttribute(phase2_rnn,
                         cudaFuncAttributeMaxDynamicSharedMemorySize, SMEM2);

    dim3 g1(DOUT / 64, (B_ * T_) / 128);       // (16, 256)
    phase1_gemm<<<g1, 256>>>(x, W_in, b_in, out);
    phase2_rnn<<<NB2, 512, SMEM2>>>(W_h, periods, shifts, out);
}